// round 9
// baseline (speedup 1.0000x reference)
#include <cuda_runtime.h>
#include <cuda_fp16.h>
#include <cstdint>
#include <cstddef>

// Problem constants
#define B_  8
#define T_  1024
#define E_  1024
#define H_  16
#define DH_ 64
#define M_TOK (B_ * T_)        // 8192 tokens
#define E2_ ((size_t)E_ * E_)

// ---------------------------------------------------------------------------
// Scratch (no cudaMalloc allowed -> __device__ globals)
// ---------------------------------------------------------------------------
__device__ __half g_qh[(size_t)M_TOK * 3 * E_];     // 48 MB  qkv hi (k/v single)
__device__ __half g_ql[(size_t)M_TOK * 3 * E_];     // 48 MB  qkv lo (Q cols only)
__device__ __half g_ah[(size_t)M_TOK * E_];         // 16 MB  att (single fp16)
__device__ __half g_th[(size_t)M_TOK * E_];         // 16 MB  x (single fp16)
__device__ __half g_wh[(size_t)3 * E_ * E_];        // 6 MB   w_in / Wo^T+Wf
__device__ __half g_wl[(size_t)2 * E_ * E_];        // 4 MB   Wc single
__device__ float g_biasf[E_];                       // fused bias
__device__ float g_zero[E_];                        // zeros (.bss)

// ---------------------------------------------------------------------------
// PTX helpers (portable sm_80+ only; target is base sm_100)
// ---------------------------------------------------------------------------
__device__ __forceinline__ uint32_t smem_to_u32(const void* p) {
    uint32_t a;
    asm("{ .reg .u64 t; cvta.to.shared.u64 t, %1; cvt.u32.u64 %0, t; }"
        : "=r"(a) : "l"(p));
    return a;
}

#define CP_ASYNC16(dst, src) \
    asm volatile("cp.async.cg.shared.global [%0], [%1], 16;" \
                 :: "r"(dst), "l"(src) : "memory")
#define CP_COMMIT() asm volatile("cp.async.commit_group;" ::: "memory")
#define CP_WAIT(n)  asm volatile("cp.async.wait_group %0;" :: "n"(n) : "memory")

#define LDSM_X4(r, addr) \
    asm volatile("ldmatrix.sync.aligned.m8n8.x4.shared.b16 {%0,%1,%2,%3}, [%4];" \
                 : "=r"((r)[0]), "=r"((r)[1]), "=r"((r)[2]), "=r"((r)[3]) \
                 : "r"(addr))
#define LDSM_X2(r, addr) \
    asm volatile("ldmatrix.sync.aligned.m8n8.x2.shared.b16 {%0,%1}, [%2];" \
                 : "=r"((r)[0]), "=r"((r)[1]) : "r"(addr))
#define LDSM_X2T(r, addr) \
    asm volatile("ldmatrix.sync.aligned.m8n8.x2.trans.shared.b16 {%0,%1}, [%2];" \
                 : "=r"((r)[0]), "=r"((r)[1]) : "r"(addr))

#define MMA_F16(c, a, b0, b1) \
    asm volatile("mma.sync.aligned.m16n8k16.row.col.f32.f16.f16.f32 " \
                 "{%0,%1,%2,%3}, {%4,%5,%6,%7}, {%8,%9}, {%0,%1,%2,%3};" \
                 : "+f"((c)[0]), "+f"((c)[1]), "+f"((c)[2]), "+f"((c)[3]) \
                 : "r"((a)[0]), "r"((a)[1]), "r"((a)[2]), "r"((a)[3]), \
                   "r"(b0), "r"(b1))

__device__ __forceinline__ uint32_t pack_h2(__half a, __half b) {
    __half2 t = __halves2half2(a, b);
    return *reinterpret_cast<uint32_t*>(&t);
}

// split 2 floats into hi/lo fp16x2 words; returns hi, writes lo
__device__ __forceinline__ uint32_t pack_hi2(float x, float y, uint32_t& lo) {
    __half hx = __float2half_rn(x), hy = __float2half_rn(y);
    __half lx = __float2half_rn(x - __half2float(hx));
    __half ly = __float2half_rn(y - __half2float(hy));
    lo = pack_h2(lx, ly);
    return pack_h2(hx, hy);
}

// ---------------------------------------------------------------------------
// fp32 -> single fp16 convert, vectorized
// ---------------------------------------------------------------------------
__global__ void convert_kernel(const float* __restrict__ x,
                               __half* __restrict__ hi, int n4) {
    int i = blockIdx.x * blockDim.x + threadIdx.x;
    int stride = gridDim.x * blockDim.x;
    for (; i < n4; i += stride) {
        float4 v = ((const float4*)x)[i];
        ((uint2*)hi)[i] = make_uint2(
            pack_h2(__float2half_rn(v.x), __float2half_rn(v.y)),
            pack_h2(__float2half_rn(v.z), __float2half_rn(v.w)));
    }
}

// fp32 [E,E] -> transposed single fp16 [E,E] (out[i][j] = in[j][i])
__global__ void transpose_convert_kernel(const float* __restrict__ x,
                                         __half* __restrict__ hi) {
    __shared__ float tile[32][33];
    const int bx = blockIdx.x * 32, by = blockIdx.y * 32;
    const int tx = threadIdx.x, ty = threadIdx.y;     // 32 x 8
#pragma unroll
    for (int u = 0; u < 4; u++)
        tile[ty + u * 8][tx] = x[(size_t)(by + ty + u * 8) * E_ + bx + tx];
    __syncthreads();
#pragma unroll
    for (int u = 0; u < 4; u++) {
        int r = ty + u * 8;
        hi[(size_t)(bx + r) * E_ + by + tx] = __float2half_rn(tile[tx][r]);
    }
}

// fused bias: bf[n] = bc[n] + sum_k bo[k] * Wc[n,k]
__global__ void bias_fuse_kernel(const float* __restrict__ wc,
                                 const float* __restrict__ bo,
                                 const float* __restrict__ bc,
                                 float* __restrict__ bf) {
    __shared__ float red[8];
    const int n = blockIdx.x, tid = threadIdx.x;
    float s = 0.f;
    for (int k = tid; k < E_; k += 256)
        s += wc[(size_t)n * E_ + k] * bo[k];
#pragma unroll
    for (int o = 16; o > 0; o >>= 1) s += __shfl_xor_sync(0xffffffffu, s, o);
    if ((tid & 31) == 0) red[tid >> 5] = s;
    __syncthreads();
    if (tid == 0) {
        float t = 0.f;
#pragma unroll
        for (int w = 0; w < 8; w++) t += red[w];
        bf[n] = t + bc[n];
    }
}

// ---------------------------------------------------------------------------
// single x single fp16 GEMM: C = A * B^T + bias  (fp32 accum)
// A: [M,K] fp16. B: [N,K] fp16.
// out_f16=0 -> Cf fp32;  out_f16=1 -> Ch hi (+ Cl lo for cols < lo_cols).
// cols < scale_cols get *0.125 (exact) -- folds 1/sqrt(dh) into Q.
// Block 128x128, 8 warps (64x32), KC=32, 3-stage cp.async, 1 sync/chunk.
// stage layout: A[0,8K) | B[8K,16K)
// ---------------------------------------------------------------------------
#define KC 32
#define STAGE_B 16384
#define NSTAGE 3
#define GEMM_SMEM (NSTAGE * STAGE_B)   // 49152

__global__ __launch_bounds__(256)
void gemm_mma(const __half* __restrict__ A,
              const __half* __restrict__ Bs,
              const float* __restrict__ bias,
              float* __restrict__ Cf,
              __half* __restrict__ Ch,
              __half* __restrict__ Cl,
              int M, int N, int K, int out_f16, int scale_cols, int lo_cols)
{
    extern __shared__ char smem[];
    const uint32_t sbase = smem_to_u32(smem);
    const int tid  = threadIdx.x;
    const int wid  = tid >> 5;
    const int lane = tid & 31;
    const int warpM = (wid >> 2) * 64;
    const int warpN = (wid & 3) * 32;
    const int rowA = blockIdx.y * 128;
    const int rowB = blockIdx.x * 128;

    float acc[4][4][4];
#pragma unroll
    for (int mt = 0; mt < 4; mt++)
#pragma unroll
        for (int nt = 0; nt < 4; nt++)
#pragma unroll
            for (int r = 0; r < 4; r++) acc[mt][nt][r] = 0.f;

    const int idx0 = tid * 2;
    const int NC = K / KC;

    auto load_stage = [&](int c, int s) {
        const uint32_t sb = sbase + s * STAGE_B;
#pragma unroll
        for (int e = 0; e < 2; e++) {
            int idx  = idx0 + e;
            int row  = idx >> 2;
            int unit = idx & 3;
            uint32_t soff = (uint32_t)(row * 64 + ((unit ^ ((row >> 1) & 3)) << 4));
            size_t goffA = ((size_t)(rowA + row) * K + c * KC + unit * 8) * 2;
            size_t goffB = ((size_t)(rowB + row) * K + c * KC + unit * 8) * 2;
            CP_ASYNC16(sb + soff,        (const char*)A  + goffA);
            CP_ASYNC16(sb + 8192 + soff, (const char*)Bs + goffB);
        }
    };

    load_stage(0, 0);
    CP_COMMIT();
    if (NC > 1) { load_stage(1, 1); CP_COMMIT(); }

    // A ldmatrix x4 lane mapping (16 rows x 2 k-halves)
    const int a_row_in = (lane & 7) + ((lane >> 3) & 1) * 8;
    const int a_ksub   = (lane >> 4);
    // B ldmatrix x4 lane mapping: n-tile pair (16 rows) x 2 k-halves
    const int b_row_in = (lane & 7) + (lane >> 4) * 8;   // row within 16-row pair
    const int b_ksub   = (lane >> 3) & 1;                // k-half select

    for (int c = 0; c < NC; c++) {
        if (c + 1 < NC) CP_WAIT(1); else CP_WAIT(0);
        __syncthreads();

        if (c + 2 < NC) { load_stage(c + 2, (c + 2) % NSTAGE); CP_COMMIT(); }

        const uint32_t sb = sbase + (c % NSTAGE) * STAGE_B;

#pragma unroll
        for (int j = 0; j < 2; j++) {
            uint32_t aF[4][4];
            uint32_t bF[2][4];
            const int aunit = j * 2 + a_ksub;
            const int bunit = j * 2 + b_ksub;
#pragma unroll
            for (int mt = 0; mt < 4; mt++) {
                int row = warpM + mt * 16 + a_row_in;
                uint32_t xo = ((aunit ^ ((row >> 1) & 3)) << 4);
                LDSM_X4(aF[mt], sb + row * 64 + xo);
            }
#pragma unroll
            for (int pr = 0; pr < 2; pr++) {
                int row = warpN + pr * 16 + b_row_in;
                uint32_t xo = ((bunit ^ ((row >> 1) & 3)) << 4);
                LDSM_X4(bF[pr], sb + 8192 + row * 64 + xo);
            }
#pragma unroll
            for (int mt = 0; mt < 4; mt++)
#pragma unroll
                for (int pr = 0; pr < 2; pr++) {
                    MMA_F16(acc[mt][2 * pr],     aF[mt], bF[pr][0], bF[pr][1]);
                    MMA_F16(acc[mt][2 * pr + 1], aF[mt], bF[pr][2], bF[pr][3]);
                }
        }
    }

    // epilogue
    const int erow = lane >> 2;
    const int ecol = (lane & 3) * 2;
#pragma unroll
    for (int mt = 0; mt < 4; mt++) {
#pragma unroll
        for (int nt = 0; nt < 4; nt++) {
            int gr = rowA + warpM + mt * 16 + erow;
            int gc = rowB + warpN + nt * 8 + ecol;
            float b0 = __ldg(bias + gc);
            float b1 = __ldg(bias + gc + 1);
            float sc = (gc < scale_cols) ? 0.125f : 1.0f;
            float v00 = (acc[mt][nt][0] + b0) * sc;
            float v01 = (acc[mt][nt][1] + b1) * sc;
            float v10 = (acc[mt][nt][2] + b0) * sc;
            float v11 = (acc[mt][nt][3] + b1) * sc;
            if (out_f16) {
                uint32_t lo0, lo1, hi0, hi1;
                hi0 = pack_hi2(v00, v01, lo0);
                hi1 = pack_hi2(v10, v11, lo1);
                *(uint32_t*)(Ch + (size_t)gr * N + gc)       = hi0;
                *(uint32_t*)(Ch + (size_t)(gr + 8) * N + gc) = hi1;
                if (gc < lo_cols) {
                    *(uint32_t*)(Cl + (size_t)gr * N + gc)       = lo0;
                    *(uint32_t*)(Cl + (size_t)(gr + 8) * N + gc) = lo1;
                }
            } else {
                *(float2*)(Cf + (size_t)gr * N + gc)       = make_float2(v00, v01);
                *(float2*)(Cf + (size_t)(gr + 8) * N + gc) = make_float2(v10, v11);
            }
        }
    }
}

// ---------------------------------------------------------------------------
// Flash attention, fp16: S = (Qh+Ql)K, O = (Ph+Pl)V (K,V single fp16).
// Output single fp16 (att feeds a single-single GEMM).
// smem: Qh|Ql (16 KB) + 2 stages x (K|V = 16 KB) = 48 KB.
// ---------------------------------------------------------------------------
#define ATTN_SMEM (16384 + 2 * 16384)

__global__ __launch_bounds__(128, 2)
void attn_mma(const __half* __restrict__ qkvh,
              const __half* __restrict__ qkvl,
              __half* __restrict__ oh)
{
    extern __shared__ char smem[];
    const uint32_t sbase = smem_to_u32(smem);
    const int tid  = threadIdx.x;
    const int lane = tid & 31;
    const int warp = tid >> 5;
    const int qt = blockIdx.x;
    const int bh = blockIdx.y;
    const int b = bh >> 4;
    const int h = bh & 15;

    const uint32_t sQh = sbase;
    const uint32_t sQl = sbase + 8192;

    const size_t tok0 = (size_t)b * T_;
    const size_t rs = 3 * E_;

    {
        const __half* qb_h = qkvh + (tok0 + qt * 64) * rs + h * DH_;
        const __half* qb_l = qkvl + (tok0 + qt * 64) * rs + h * DH_;
#pragma unroll
        for (int it = 0; it < 4; it++) {
            int idx = tid + it * 128;
            int row = idx >> 3, unit = idx & 7;
            uint32_t off = (uint32_t)(row * 128 + ((unit ^ (row & 7)) << 4));
            CP_ASYNC16(sQh + off, (const char*)(qb_h + (size_t)row * rs) + unit * 16);
            CP_ASYNC16(sQl + off, (const char*)(qb_l + (size_t)row * rs) + unit * 16);
        }
    }

    auto load_kv = [&](int kt, int s) {
        uint32_t sb = sbase + 16384 + s * 16384;
        const __half* kh = qkvh + (tok0 + kt * 64) * rs + E_ + h * DH_;
#pragma unroll
        for (int it = 0; it < 4; it++) {
            int idx = tid + it * 128;
            int row = idx >> 3, unit = idx & 7;
            uint32_t off = (uint32_t)(row * 128 + ((unit ^ (row & 7)) << 4));
            size_t g = (size_t)row * rs;
            CP_ASYNC16(sb +        off, (const char*)(kh + g) + unit * 16);
            CP_ASYNC16(sb + 8192 + off, (const char*)(kh + E_ + g) + unit * 16);
        }
    };

    load_kv(0, 0);
    CP_COMMIT();

    const int tl   = lane & 15;
    const int arow = warp * 16 + tl;
    const int aun  = lane >> 4;
    const int brw  = tl & 7;
    const int bks  = (tl >> 3) & 1;

    float O[8][4];
#pragma unroll
    for (int t = 0; t < 8; t++)
#pragma unroll
        for (int r = 0; r < 4; r++) O[t][r] = 0.f;
    float m0 = -1e30f, m1 = -1e30f, l0 = 0.f, l1 = 0.f;

    uint32_t qH[4][4], qL[4][4];
    bool qloaded = false;

    for (int kt = 0; kt <= qt; kt++) {
        CP_WAIT(0);
        __syncthreads();
        if (kt < qt) { load_kv(kt + 1, (kt + 1) & 1); CP_COMMIT(); }

        if (!qloaded) {
            qloaded = true;
#pragma unroll
            for (int j = 0; j < 4; j++) {
                int au = j * 2 + aun;
                uint32_t aoff = (uint32_t)(arow * 128 + ((au ^ (arow & 7)) << 4));
                LDSM_X4(qH[j], sQh + aoff);
                LDSM_X4(qL[j], sQl + aoff);
            }
        }

        const uint32_t sb = sbase + 16384 + (kt & 1) * 16384;
        const uint32_t sK = sb, sV = sb + 8192;

        float S[8][4];
#pragma unroll
        for (int t = 0; t < 8; t++)
#pragma unroll
            for (int r = 0; r < 4; r++) S[t][r] = 0.f;

#pragma unroll
        for (int j = 0; j < 4; j++) {
#pragma unroll
            for (int t = 0; t < 8; t++) {
                int r = t * 8 + brw;
                int u = j * 2 + bks;
                uint32_t boff = (uint32_t)(r * 128 + ((u ^ (r & 7)) << 4));
                uint32_t bF[2];
                LDSM_X2(bF, sK + boff);
                MMA_F16(S[t], qH[j], bF[0], bF[1]);
                MMA_F16(S[t], qL[j], bF[0], bF[1]);
            }
        }

        if (kt == qt) {
            int r0 = warp * 16 + (lane >> 2);
#pragma unroll
            for (int t = 0; t < 8; t++) {
                int c = t * 8 + (lane & 3) * 2;
                if (c     > r0)     S[t][0] = -1e30f;
                if (c + 1 > r0)     S[t][1] = -1e30f;
                if (c     > r0 + 8) S[t][2] = -1e30f;
                if (c + 1 > r0 + 8) S[t][3] = -1e30f;
            }
        }

        float rm0 = -1e30f, rm1 = -1e30f;
#pragma unroll
        for (int t = 0; t < 8; t++) {
            rm0 = fmaxf(rm0, fmaxf(S[t][0], S[t][1]));
            rm1 = fmaxf(rm1, fmaxf(S[t][2], S[t][3]));
        }
        rm0 = fmaxf(rm0, __shfl_xor_sync(0xffffffffu, rm0, 1));
        rm0 = fmaxf(rm0, __shfl_xor_sync(0xffffffffu, rm0, 2));
        rm1 = fmaxf(rm1, __shfl_xor_sync(0xffffffffu, rm1, 1));
        rm1 = fmaxf(rm1, __shfl_xor_sync(0xffffffffu, rm1, 2));
        float mn0 = fmaxf(m0, rm0), mn1 = fmaxf(m1, rm1);
        float al0 = __expf(m0 - mn0), al1 = __expf(m1 - mn1);
        m0 = mn0; m1 = mn1;

        float ls0 = 0.f, ls1 = 0.f;
#pragma unroll
        for (int t = 0; t < 8; t++) {
            S[t][0] = __expf(S[t][0] - mn0); ls0 += S[t][0];
            S[t][1] = __expf(S[t][1] - mn0); ls0 += S[t][1];
            S[t][2] = __expf(S[t][2] - mn1); ls1 += S[t][2];
            S[t][3] = __expf(S[t][3] - mn1); ls1 += S[t][3];
        }
        l0 = l0 * al0 + ls0;
        l1 = l1 * al1 + ls1;
#pragma unroll
        for (int t = 0; t < 8; t++) {
            O[t][0] *= al0; O[t][1] *= al0;
            O[t][2] *= al1; O[t][3] *= al1;
        }

        uint32_t pH[4][4], pL[4][4];
#pragma unroll
        for (int j = 0; j < 4; j++) {
            pH[j][0] = pack_hi2(S[2*j][0],   S[2*j][1],   pL[j][0]);
            pH[j][1] = pack_hi2(S[2*j][2],   S[2*j][3],   pL[j][1]);
            pH[j][2] = pack_hi2(S[2*j+1][0], S[2*j+1][1], pL[j][2]);
            pH[j][3] = pack_hi2(S[2*j+1][2], S[2*j+1][3], pL[j][3]);
        }

#pragma unroll
        for (int j = 0; j < 4; j++) {
            int vr = j * 16 + brw + bks * 8;
#pragma unroll
            for (int t = 0; t < 8; t++) {
                uint32_t voff = (uint32_t)(vr * 128 + ((t ^ (vr & 7)) << 4));
                uint32_t vF[2];
                LDSM_X2T(vF, sV + voff);
                MMA_F16(O[t], pH[j], vF[0], vF[1]);
                MMA_F16(O[t], pL[j], vF[0], vF[1]);
            }
        }
    }

    l0 += __shfl_xor_sync(0xffffffffu, l0, 1);
    l0 += __shfl_xor_sync(0xffffffffu, l0, 2);
    l1 += __shfl_xor_sync(0xffffffffu, l1, 1);
    l1 += __shfl_xor_sync(0xffffffffu, l1, 2);
    float inv0 = 1.f / l0, inv1 = 1.f / l1;

    int r0 = qt * 64 + warp * 16 + (lane >> 2);
    size_t grow0 = (tok0 + r0) * E_ + h * DH_;
    size_t grow1 = grow0 + (size_t)8 * E_;
#pragma unroll
    for (int t = 0; t < 8; t++) {
        int c = t * 8 + (lane & 3) * 2;
        *(uint32_t*)(oh + grow0 + c) =
            pack_h2(__float2half_rn(O[t][0] * inv0), __float2half_rn(O[t][1] * inv0));
        *(uint32_t*)(oh + grow1 + c) =
            pack_h2(__float2half_rn(O[t][2] * inv1), __float2half_rn(O[t][3] * inv1));
    }
}

// ---------------------------------------------------------------------------
// kernel_launch
// inputs: x, in_proj_w, in_proj_b, out_proj_w, out_proj_b, c_proj_w, c_proj_b
// ---------------------------------------------------------------------------
extern "C" void kernel_launch(void* const* d_in, const int* in_sizes, int n_in,
                              void* d_out, int out_size)
{
    const float* x     = (const float*)d_in[0];
    const float* w_in  = (const float*)d_in[1];
    const float* b_in  = (const float*)d_in[2];
    const float* w_out = (const float*)d_in[3];
    const float* b_out = (const float*)d_in[4];
    const float* w_c   = (const float*)d_in[5];
    const float* b_c   = (const float*)d_in[6];
    float* out = (float*)d_out;

    __half *qh, *ql, *ah, *th, *wh, *wl;
    float *biasf, *zerov;
    cudaGetSymbolAddress((void**)&qh, g_qh);
    cudaGetSymbolAddress((void**)&ql, g_ql);
    cudaGetSymbolAddress((void**)&ah, g_ah);
    cudaGetSymbolAddress((void**)&th, g_th);
    cudaGetSymbolAddress((void**)&wh, g_wh);
    cudaGetSymbolAddress((void**)&wl, g_wl);
    cudaGetSymbolAddress((void**)&biasf, g_biasf);
    cudaGetSymbolAddress((void**)&zerov, g_zero);

    cudaFuncSetAttribute(gemm_mma,
                         cudaFuncAttributeMaxDynamicSharedMemorySize, GEMM_SMEM);
    cudaFuncSetAttribute(attn_mma,
                         cudaFuncAttributeMaxDynamicSharedMemorySize, ATTN_SMEM);

    const int NA4   = M_TOK * E_ / 4;
    const int NWIN4 = 3 * E_ * E_ / 4;
    const int NW4   = E_ * E_ / 4;

    // 1) convert x and in_proj_w to fp16
    convert_kernel<<<1024, 256>>>(x, th, NA4);
    convert_kernel<<<1024, 256>>>(w_in, wh, NWIN4);

    // 2) QKV GEMM -> fp16 qkv hi (+ lo for Q cols), Q cols scaled by 1/8
    gemm_mma<<<dim3(3 * E_ / 128, M_TOK / 128), 256, GEMM_SMEM>>>(
        th, wh, b_in, nullptr, qh, ql, M_TOK, 3 * E_, E_, 1, E_, E_);

    // 3) flash attention -> att single fp16
    attn_mma<<<dim3(T_ / 64, B_ * H_), 128, ATTN_SMEM>>>(qh, ql, ah);

    // 4) fused projection weight: Wf = Wc * Wo  (and fused bias)
    //    wh[0..E2)   = Wo^T single fp16 (w_in consumed)
    //    wl[0..E2)   = Wc single fp16
    //    wh[E2..2E2) = Wf single fp16
    transpose_convert_kernel<<<dim3(32, 32), dim3(32, 8)>>>(w_out, wh);
    convert_kernel<<<1024, 256>>>(w_c, wl, NW4);
    bias_fuse_kernel<<<E_, 256>>>(w_c, b_out, b_c, biasf);
    gemm_mma<<<dim3(E_ / 128, E_ / 128), 256, GEMM_SMEM>>>(
        wl, wh, zerov, nullptr, wh + E2_, nullptr, E_, E_, E_, 1, 0, 0);

    // 5) single fused output GEMM: out = att * Wf^T + biasf  (fp32)
    gemm_mma<<<dim3(E_ / 128, M_TOK / 128), 256, GEMM_SMEM>>>(
        ah, wh + E2_, biasf, out, nullptr, nullptr, M_TOK, E_, E_, 0, 0, 0);
}